// round 5
// baseline (speedup 1.0000x reference)
#include <cuda_runtime.h>
#include <cstdint>

#define BB 32
#define SS 8192
#define DD 64
#define FF 128
#define CS 64
#define NCH (SS / CS)   // 128 chunks

// Cross-CTA scan state (zeroed flags each launch by zero_flags)
__device__ float g_aggA[NCH * BB * FF];
__device__ float g_aggC[NCH * BB * FF];
__device__ int   g_flag[NCH * BB];

__global__ void zero_flags()
{
    const int i = blockIdx.x * 256 + threadIdx.x;
    if (i < NCH * BB) g_flag[i] = 0;
}

// Permuted column index: value for feature-col f lives at colp(f) within a
// 128-wide smem row. Makes warp LDS.128/STS.128 dense (conflict-free).
__device__ __forceinline__ int colp(int f) {
    return ((f & 4) << 4) + ((f >> 3) << 2) + (f & 3);
}

// SMEM float offsets
#define SMW 0                      // W:  64 x 128 (permuted cols)     8192
#define SME 8192                   // E^T: 16 k x 68 (pitch 68)        1088
#define SMA 9280                   // A:  64 x 132 (pitch, perm cols)  8448
#define SMV 17728                  // VC: 64 x 132 (v_f then c)        8448
#define SM_FLOATS 26176            // = 104704 bytes

#define FMA4(acc, s, wv)                          \
    do {                                          \
        (acc).x = fmaf((s), (wv).x, (acc).x);     \
        (acc).y = fmaf((s), (wv).y, (acc).y);     \
        (acc).z = fmaf((s), (wv).z, (acc).z);     \
        (acc).w = fmaf((s), (wv).w, (acc).w);     \
    } while (0)

// One feature GEMM: exp(x[rows 0..63][0..63]) @ W -> acc0/acc1 (4 rows x 8 cols)
#define GEMM_INPUT(xptr)                                                      \
    do {                                                                      \
        _Pragma("unroll")                                                     \
        for (int _i = 0; _i < 4; _i++) {                                      \
            acc0[_i] = make_float4(0.f, 0.f, 0.f, 0.f);                       \
            acc1[_i] = make_float4(0.f, 0.f, 0.f, 0.f);                       \
        }                                                                     \
        for (int kb = 0; kb < 4; kb++) {                                      \
            {                                                                 \
                const int s_ = tid >> 2, c4 = tid & 3;                        \
                float4 xv = *(const float4*)&(xptr)[(size_t)s_ * DD + kb * 16 + c4 * 4]; \
                sm[SME + (c4 * 4 + 0) * 68 + s_] = __expf(xv.x);              \
                sm[SME + (c4 * 4 + 1) * 68 + s_] = __expf(xv.y);              \
                sm[SME + (c4 * 4 + 2) * 68 + s_] = __expf(xv.z);              \
                sm[SME + (c4 * 4 + 3) * 68 + s_] = __expf(xv.w);              \
            }                                                                 \
            __syncthreads();                                                  \
            _Pragma("unroll")                                                 \
            for (int kk = 0; kk < 16; kk++) {                                 \
                const float4 av = *(const float4*)&sm[SME + kk * 68 + s0];    \
                const float4 w0 = *(const float4*)&sm[SMW + (kb * 16 + kk) * 128 + tf * 4];      \
                const float4 w1 = *(const float4*)&sm[SMW + (kb * 16 + kk) * 128 + 64 + tf * 4]; \
                FMA4(acc0[0], av.x, w0);  FMA4(acc1[0], av.x, w1);            \
                FMA4(acc0[1], av.y, w0);  FMA4(acc1[1], av.y, w1);            \
                FMA4(acc0[2], av.z, w0);  FMA4(acc1[2], av.z, w1);            \
                FMA4(acc0[3], av.w, w0);  FMA4(acc1[3], av.w, w1);            \
            }                                                                 \
            __syncthreads();                                                  \
        }                                                                     \
    } while (0)

#define GATE4(dst, src)                                                       \
    do {                                                                      \
        (dst).x = ((src).x > 0.5f) ? (src).x : 0.f;                           \
        (dst).y = ((src).y > 0.5f) ? (src).y : 0.f;                           \
        (dst).z = ((src).z > 0.5f) ? (src).z : 0.f;                           \
        (dst).w = ((src).w > 0.5f) ? (src).w : 0.f;                           \
    } while (0)

// ---------------------------------------------------------------------------
// Fused kernel: features (FFMA GEMM) + gates + single-pass chunked scan
// (decoupled lookback) + output. CTA = 64 s-rows x 128 F, 256 threads.
// Grid: x = b (32), y = ch (128) -> linear bid = ch*32+b (chunk-major order).
// ---------------------------------------------------------------------------
__global__ __launch_bounds__(256, 2)
void fused_sla(const float* __restrict__ q, const float* __restrict__ k,
               const float* __restrict__ v, const float* __restrict__ w,
               float* __restrict__ out)
{
    extern __shared__ float sm[];
    const int tid = threadIdx.x;
    const int tf  = tid & 15;          // f-thread: cols [tf*8, tf*8+8)
    const int ts  = tid >> 4;          // s-thread: rows [ts*4, ts*4+4)
    const int s0  = ts * 4;
    const int b   = blockIdx.x;
    const int ch  = blockIdx.y;
    const size_t ibase = ((size_t)b * SS + ch * CS) * DD;

    // Load W into smem with permuted columns (coalesced gmem read)
#pragma unroll
    for (int g4 = tid; g4 < 2048; g4 += 256) {
        const float4 wv = ((const float4*)w)[g4];
        const int k_ = g4 >> 5, g = g4 & 31;
        *(float4*)&sm[SMW + k_ * 128 + ((g & 1) << 6) + ((g >> 1) << 2)] = wv;
    }
    // (first __syncthreads inside GEMM_INPUT covers W visibility)

    float4 acc0[4], acc1[4];

    // ===== V: features -> sVC =====
    GEMM_INPUT(v + ibase);
#pragma unroll
    for (int i = 0; i < 4; i++) {
        const int row = s0 + i;
        *(float4*)&sm[SMV + row * 132 + tf * 4]      = acc0[i];
        *(float4*)&sm[SMV + row * 132 + 64 + tf * 4] = acc1[i];
    }
    __syncthreads();

    // ===== K: features -> gate -> a (sA), c = a*v_f (overwrites sVC) =====
    GEMM_INPUT(k + ibase);
#pragma unroll
    for (int i = 0; i < 4; i++) {
        const int row = s0 + i;
        const float4 vf0 = *(const float4*)&sm[SMV + row * 132 + tf * 4];
        const float4 vf1 = *(const float4*)&sm[SMV + row * 132 + 64 + tf * 4];
        float4 a0, a1, c0, c1;
        GATE4(a0, acc0[i]);
        GATE4(a1, acc1[i]);
        c0.x = a0.x * vf0.x; c0.y = a0.y * vf0.y;
        c0.z = a0.z * vf0.z; c0.w = a0.w * vf0.w;
        c1.x = a1.x * vf1.x; c1.y = a1.y * vf1.y;
        c1.z = a1.z * vf1.z; c1.w = a1.w * vf1.w;
        *(float4*)&sm[SMA + row * 132 + tf * 4]      = a0;
        *(float4*)&sm[SMA + row * 132 + 64 + tf * 4] = a1;
        *(float4*)&sm[SMV + row * 132 + tf * 4]      = c0;
        *(float4*)&sm[SMV + row * 132 + 64 + tf * 4] = c1;
    }
    __syncthreads();

    // ===== publish chunk aggregates =====
    if (tid < FF) {
        const int c = colp(tid);
        float sA_ = 0.f, sC_ = 0.f;
#pragma unroll 8
        for (int s = 0; s < CS; s++) {
            sA_ += sm[SMA + s * 132 + c];
            sC_ += sm[SMV + s * 132 + c];
        }
        g_aggA[((size_t)ch * BB + b) * FF + tid] = sA_;
        g_aggC[((size_t)ch * BB + b) * FF + tid] = sC_;
        __threadfence();
    }
    __syncthreads();
    if (tid == 0) atomicExch(&g_flag[ch * BB + b], 1);

    // ===== Q: features -> gated q_s kept in registers =====
    GEMM_INPUT(q + ibase);
#pragma unroll
    for (int i = 0; i < 4; i++) {
        float4 t;
        GATE4(t, acc0[i]); acc0[i] = t;
        GATE4(t, acc1[i]); acc1[i] = t;
    }

    // ===== lookback: wait for all predecessor chunks, sum aggregates =====
    if (tid == 0) {
        for (int p = 0; p < ch; p++)
            while (((volatile int*)g_flag)[p * BB + b] == 0) __nanosleep(64);
    }
    __syncthreads();

    float prefA = 0.f, prefC = 0.f;
    if (tid < FF) {
#pragma unroll 4
        for (int p = 0; p < ch; p++) {
            prefA += g_aggA[((size_t)p * BB + b) * FF + tid];
            prefC += g_aggC[((size_t)p * BB + b) * FF + tid];
        }
    }

    // ===== in-chunk sequential scan: ratio -> sA (in place) =====
    if (tid < FF) {
        const int c = colp(tid);
        float cA = prefA, cC = prefC;
#pragma unroll 4
        for (int s = 0; s < CS; s++) {
            cA += sm[SMA + s * 132 + c];
            cC += sm[SMV + s * 132 + c];
            sm[SMA + s * 132 + c] = __fdividef(cC + 1e-8f, cA + 1e-8f);
        }
    }
    __syncthreads();

    // ===== output: out = q_s * ratio =====
    const size_t ob = ((size_t)b * SS + ch * CS) * FF;
#pragma unroll
    for (int i = 0; i < 4; i++) {
        const int row = s0 + i;
        const float4 r0 = *(const float4*)&sm[SMA + row * 132 + tf * 4];
        const float4 r1 = *(const float4*)&sm[SMA + row * 132 + 64 + tf * 4];
        float4 o0, o1;
        o0.x = acc0[i].x * r0.x; o0.y = acc0[i].y * r0.y;
        o0.z = acc0[i].z * r0.z; o0.w = acc0[i].w * r0.w;
        o1.x = acc1[i].x * r1.x; o1.y = acc1[i].y * r1.y;
        o1.z = acc1[i].z * r1.z; o1.w = acc1[i].w * r1.w;
        *(float4*)&out[ob + (size_t)row * FF + tf * 8]     = o0;
        *(float4*)&out[ob + (size_t)row * FF + tf * 8 + 4] = o1;
    }
}

extern "C" void kernel_launch(void* const* d_in, const int* in_sizes, int n_in,
                              void* d_out, int out_size)
{
    const float* q = (const float*)d_in[0];
    const float* k = (const float*)d_in[1];
    const float* v = (const float*)d_in[2];
    const float* w = (const float*)d_in[3];
    float* out = (float*)d_out;

    zero_flags<<<(NCH * BB + 255) / 256, 256>>>();

    cudaFuncSetAttribute(fused_sla, cudaFuncAttributeMaxDynamicSharedMemorySize,
                         SM_FLOATS * 4);
    dim3 grid(BB, NCH);   // linear bid = ch*BB + b  (chunk-major)
    fused_sla<<<grid, 256, SM_FLOATS * 4>>>(q, k, v, w, out);
}

// round 6
// speedup vs baseline: 1.5473x; 1.5473x over previous
#include <cuda_runtime.h>
#include <cstdint>

#define BB 32
#define SS 8192
#define DD 64
#define FF 128
#define CS 64
#define NCH (SS / CS)   // 128 chunks

// Cross-CTA scan state (flags zeroed each launch)
__device__ float g_aggA[NCH * BB * FF];
__device__ float g_aggC[NCH * BB * FF];
__device__ int   g_flag[NCH * BB];

__global__ void zero_flags()
{
    const int i = blockIdx.x * 256 + threadIdx.x;
    if (i < NCH * BB) g_flag[i] = 0;
}

// SMEM float offsets (total 26752 floats = 104.5 KB -> 2 CTAs/SM)
#define SMW 0        // W: 64 k-rows x 128 cols            8192
#define SME 8192     // E^T: 32 k-rows x 64 s (pitch 68)   2176
#define SMA 10368    // A  (k_s): 64 s x 128 f             8192
#define SMV 18560    // VC (v_f then c): 64 s x 128 f      8192
#define SM_FLOATS 26752

#define FMA4(acc, s, wv)                          \
    do {                                          \
        (acc).x = fmaf((s), (wv).x, (acc).x);     \
        (acc).y = fmaf((s), (wv).y, (acc).y);     \
        (acc).z = fmaf((s), (wv).z, (acc).z);     \
        (acc).w = fmaf((s), (wv).w, (acc).w);     \
    } while (0)

#define GATE4(dst, src)                                                       \
    do {                                                                      \
        (dst).x = ((src).x > 0.5f) ? (src).x : 0.f;                           \
        (dst).y = ((src).y > 0.5f) ? (src).y : 0.f;                           \
        (dst).z = ((src).z > 0.5f) ? (src).z : 0.f;                           \
        (dst).w = ((src).w > 0.5f) ? (src).w : 0.f;                           \
    } while (0)

// Load whole 64x64 input tile: thread covers row tid>>2, float4-cols {tid&3}+4j
#define LOADX(xptr)                                                           \
    do {                                                                      \
        const float4* _p4 = (const float4*)(xptr);                            \
        _Pragma("unroll")                                                     \
        for (int _j = 0; _j < 4; _j++)                                        \
            xr[_j] = _p4[xbase + 4 * _j];                                     \
    } while (0)

// exp + store k-half h of xr into E^T (32 k-rows x 64 s, pitch 68)
#define STSE(h)                                                               \
    do {                                                                      \
        const int _row = tid >> 2;                                            \
        _Pragma("unroll")                                                     \
        for (int _jj = 0; _jj < 2; _jj++) {                                   \
            const float4 _x = xr[2 * (h) + _jj];                              \
            const int _kb = 4 * (tid & 3) + 16 * _jj;                         \
            sm[SME + (_kb + 0) * 68 + _row] = __expf(_x.x);                   \
            sm[SME + (_kb + 1) * 68 + _row] = __expf(_x.y);                   \
            sm[SME + (_kb + 2) * 68 + _row] = __expf(_x.z);                   \
            sm[SME + (_kb + 3) * 68 + _row] = __expf(_x.w);                   \
        }                                                                     \
    } while (0)

// FMA over k-half h: acc0 = cols [tf*4,+4), acc1 = cols [64+tf*4,+4)
#define FMAH(h)                                                               \
    do {                                                                      \
        _Pragma("unroll 8")                                                   \
        for (int _kk = 0; _kk < 32; _kk++) {                                  \
            const float4 av = *(const float4*)&sm[SME + _kk * 68 + s0];       \
            const float4 w0 = *(const float4*)&sm[SMW + ((h) * 32 + _kk) * 128 + tf * 4];      \
            const float4 w1 = *(const float4*)&sm[SMW + ((h) * 32 + _kk) * 128 + 64 + tf * 4]; \
            FMA4(acc0[0], av.x, w0);  FMA4(acc1[0], av.x, w1);                \
            FMA4(acc0[1], av.y, w0);  FMA4(acc1[1], av.y, w1);                \
            FMA4(acc0[2], av.z, w0);  FMA4(acc1[2], av.z, w1);                \
            FMA4(acc0[3], av.w, w0);  FMA4(acc1[3], av.w, w1);                \
        }                                                                     \
    } while (0)

#define ZEROACC()                                                             \
    do {                                                                      \
        _Pragma("unroll")                                                     \
        for (int _i = 0; _i < 4; _i++) {                                      \
            acc0[_i] = make_float4(0.f, 0.f, 0.f, 0.f);                       \
            acc1[_i] = make_float4(0.f, 0.f, 0.f, 0.f);                       \
        }                                                                     \
    } while (0)

// ---------------------------------------------------------------------------
// Fused: features (FFMA) + gates + single-pass chunked scan (decoupled
// lookback) + output. CTA = 64 s-rows x 128 F, 256 threads, 2 CTAs/SM.
// Grid (BB, NCH): linear bid = ch*BB + b (chunk-major -> predecessors first).
// ---------------------------------------------------------------------------
__global__ __launch_bounds__(256, 2)
void fused_sla(const float* __restrict__ q, const float* __restrict__ k,
               const float* __restrict__ v, const float* __restrict__ w,
               float* __restrict__ out)
{
    extern __shared__ float sm[];
    const int tid = threadIdx.x;
    const int tf  = tid & 15;          // f-thread: cols tf*4.. and 64+tf*4..
    const int s0  = (tid >> 4) * 4;    // s-thread: rows s0..s0+3
    const int b   = blockIdx.x;
    const int ch  = blockIdx.y;
    const int xbase = (tid >> 2) * 16 + (tid & 3);
    const size_t ibase = ((size_t)b * SS + ch * CS) * DD;

    float4 xr[4], acc0[4], acc1[4];

    // W -> smem identity (coalesced), covered by first sync
#pragma unroll
    for (int t = 0; t < 8; t++)
        ((float4*)sm)[tid + t * 256] = ((const float4*)w)[tid + t * 256];

    // ===== V GEMM (prefetch K during second half) =====
    LOADX(v + ibase);
    ZEROACC();
    STSE(0); __syncthreads();
    FMAH(0); __syncthreads();
    STSE(1);
    LOADX(k + ibase);
    __syncthreads();
    FMAH(1);
#pragma unroll
    for (int i = 0; i < 4; i++) {
        const int row = s0 + i;
        *(float4*)&sm[SMV + row * 128 + tf * 4]      = acc0[i];
        *(float4*)&sm[SMV + row * 128 + 64 + tf * 4] = acc1[i];
    }
    __syncthreads();

    // ===== K GEMM (prefetch Q) =====
    ZEROACC();
    STSE(0); __syncthreads();
    FMAH(0); __syncthreads();
    STSE(1);
    LOADX(q + ibase);
    __syncthreads();
    FMAH(1);
#pragma unroll
    for (int i = 0; i < 4; i++) {
        const int row = s0 + i;
        const float4 vf0 = *(const float4*)&sm[SMV + row * 128 + tf * 4];
        const float4 vf1 = *(const float4*)&sm[SMV + row * 128 + 64 + tf * 4];
        float4 a0, a1, c0, c1;
        GATE4(a0, acc0[i]);
        GATE4(a1, acc1[i]);
        c0.x = a0.x * vf0.x; c0.y = a0.y * vf0.y;
        c0.z = a0.z * vf0.z; c0.w = a0.w * vf0.w;
        c1.x = a1.x * vf1.x; c1.y = a1.y * vf1.y;
        c1.z = a1.z * vf1.z; c1.w = a1.w * vf1.w;
        *(float4*)&sm[SMA + row * 128 + tf * 4]      = a0;
        *(float4*)&sm[SMA + row * 128 + 64 + tf * 4] = a1;
        *(float4*)&sm[SMV + row * 128 + tf * 4]      = c0;
        *(float4*)&sm[SMV + row * 128 + 64 + tf * 4] = c1;
    }
    __syncthreads();

    // ===== Q GEMM, with chunk aggregates published up front =====
    ZEROACC();
    STSE(0);                       // all threads stage Q half 1
    if (tid < FF) {                // warps 0-3 also compute + publish aggregates
        float sA_ = 0.f, sC_ = 0.f;
#pragma unroll 8
        for (int s = 0; s < CS; s++) {
            sA_ += sm[SMA + s * 128 + tid];
            sC_ += sm[SMV + s * 128 + tid];
        }
        g_aggA[((size_t)ch * BB + b) * FF + tid] = sA_;
        g_aggC[((size_t)ch * BB + b) * FF + tid] = sC_;
        __threadfence();
    }
    __syncthreads();
    if (tid == 0) atomicExch(&g_flag[ch * BB + b], 1);
    FMAH(0); __syncthreads();
    STSE(1); __syncthreads();
    FMAH(1);
#pragma unroll
    for (int i = 0; i < 4; i++) {
        float4 t;
        GATE4(t, acc0[i]); acc0[i] = t;
        GATE4(t, acc1[i]); acc1[i] = t;
    }

    // ===== parallel lookback wait =====
    if (tid < ch)
        while (((volatile int*)g_flag)[tid * BB + b] == 0) __nanosleep(64);
    __syncthreads();

    // ===== prefix sums over predecessor aggregates =====
    float prefA = 0.f, prefC = 0.f;
    if (tid < FF) {
#pragma unroll 4
        for (int p = 0; p < ch; p++) {
            prefA += g_aggA[((size_t)p * BB + b) * FF + tid];
            prefC += g_aggC[((size_t)p * BB + b) * FF + tid];
        }
    }

    // ===== in-chunk sequential scan: ratio written into SMA =====
    if (tid < FF) {
        float cA = prefA, cC = prefC;
#pragma unroll 4
        for (int s = 0; s < CS; s++) {
            cA += sm[SMA + s * 128 + tid];
            cC += sm[SMV + s * 128 + tid];
            sm[SMA + s * 128 + tid] = __fdividef(cC + 1e-8f, cA + 1e-8f);
        }
    }
    __syncthreads();

    // ===== output: out = q_s * ratio =====
    const size_t ob = ((size_t)b * SS + ch * CS) * FF;
#pragma unroll
    for (int i = 0; i < 4; i++) {
        const int row = s0 + i;
        const float4 r0 = *(const float4*)&sm[SMA + row * 128 + tf * 4];
        const float4 r1 = *(const float4*)&sm[SMA + row * 128 + 64 + tf * 4];
        float4 o0, o1;
        o0.x = acc0[i].x * r0.x; o0.y = acc0[i].y * r0.y;
        o0.z = acc0[i].z * r0.z; o0.w = acc0[i].w * r0.w;
        o1.x = acc1[i].x * r1.x; o1.y = acc1[i].y * r1.y;
        o1.z = acc1[i].z * r1.z; o1.w = acc1[i].w * r1.w;
        *(float4*)&out[ob + (size_t)row * FF + tf * 4]      = o0;
        *(float4*)&out[ob + (size_t)row * FF + 64 + tf * 4] = o1;
    }
}

extern "C" void kernel_launch(void* const* d_in, const int* in_sizes, int n_in,
                              void* d_out, int out_size)
{
    const float* q = (const float*)d_in[0];
    const float* k = (const float*)d_in[1];
    const float* v = (const float*)d_in[2];
    const float* w = (const float*)d_in[3];
    float* out = (float*)d_out;

    zero_flags<<<(NCH * BB + 255) / 256, 256>>>();

    cudaFuncSetAttribute(fused_sla, cudaFuncAttributeMaxDynamicSharedMemorySize,
                         SM_FLOATS * 4);
    dim3 grid(BB, NCH);   // linear bid = ch*BB + b (chunk-major)
    fused_sla<<<grid, 256, SM_FLOATS * 4>>>(q, k, v, w, out);
}

// round 7
// speedup vs baseline: 1.6579x; 1.0715x over previous
#include <cuda_runtime.h>
#include <cstdint>

#define BB 32
#define SS 8192
#define DD 64
#define FF 128
#define CS 64
#define NCH (SS / CS)   // 128 chunks

// Cross-CTA scan state (flags zeroed each launch)
__device__ float g_aggA[NCH * BB * FF];
__device__ float g_aggC[NCH * BB * FF];
__device__ int   g_flag[NCH * BB];

__global__ void zero_flags()
{
    const int i = blockIdx.x * 256 + threadIdx.x;
    if (i < NCH * BB) g_flag[i] = 0;
}

// SMEM float offsets (total 28928 floats = 113 KB -> 2 CTAs/SM)
#define SMW   0        // W: 64 k-rows x 128 cols              8192
#define SME0  8192     // E slab 0: 32 k x 64 s (pitch 68)     2176
#define SME1  10368    // E slab 1                             2176
#define SMA   12544    // A  (k_s, then cumsum): 64 x 128      8192
#define SMV   20736    // VC (v_f, c, then cumsum): 64 x 128   8192
#define SMPF  8192     // prefbuf A (reuses SME0): 128
#define SMPFC 8320     // prefbuf C: 128
#define SM_FLOATS 28928

#define FMA4(acc, s, wv)                          \
    do {                                          \
        (acc).x = fmaf((s), (wv).x, (acc).x);     \
        (acc).y = fmaf((s), (wv).y, (acc).y);     \
        (acc).z = fmaf((s), (wv).z, (acc).z);     \
        (acc).w = fmaf((s), (wv).w, (acc).w);     \
    } while (0)

#define GATE4(dst, src)                                                       \
    do {                                                                      \
        (dst).x = ((src).x > 0.5f) ? (src).x : 0.f;                           \
        (dst).y = ((src).y > 0.5f) ? (src).y : 0.f;                           \
        (dst).z = ((src).z > 0.5f) ? (src).z : 0.f;                           \
        (dst).w = ((src).w > 0.5f) ? (src).w : 0.f;                           \
    } while (0)

// Load whole 64x64 input tile into xr[4]
#define LOADX(xptr)                                                           \
    do {                                                                      \
        const float4* _p4 = (const float4*)(xptr);                            \
        _Pragma("unroll")                                                     \
        for (int _j = 0; _j < 4; _j++)                                        \
            xr[_j] = _p4[xbase + 4 * _j];                                     \
    } while (0)

// exp + store k-half h of xr into E slab at float-offset eb (pitch 68)
#define STSE(h, eb)                                                           \
    do {                                                                      \
        const int _row = tid >> 2;                                            \
        _Pragma("unroll")                                                     \
        for (int _jj = 0; _jj < 2; _jj++) {                                   \
            const float4 _x = xr[2 * (h) + _jj];                              \
            const int _kb = 4 * (tid & 3) + 16 * _jj;                         \
            sm[(eb) + (_kb + 0) * 68 + _row] = __expf(_x.x);                  \
            sm[(eb) + (_kb + 1) * 68 + _row] = __expf(_x.y);                  \
            sm[(eb) + (_kb + 2) * 68 + _row] = __expf(_x.z);                  \
            sm[(eb) + (_kb + 3) * 68 + _row] = __expf(_x.w);                  \
        }                                                                     \
    } while (0)

// FMA over k-half h reading E slab at eb
#define FMAH(h, eb)                                                           \
    do {                                                                      \
        _Pragma("unroll 8")                                                   \
        for (int _kk = 0; _kk < 32; _kk++) {                                  \
            const float4 av = *(const float4*)&sm[(eb) + _kk * 68 + s0];      \
            const float4 w0 = *(const float4*)&sm[SMW + ((h) * 32 + _kk) * 128 + tf * 4];      \
            const float4 w1 = *(const float4*)&sm[SMW + ((h) * 32 + _kk) * 128 + 64 + tf * 4]; \
            FMA4(acc0[0], av.x, w0);  FMA4(acc1[0], av.x, w1);                \
            FMA4(acc0[1], av.y, w0);  FMA4(acc1[1], av.y, w1);                \
            FMA4(acc0[2], av.z, w0);  FMA4(acc1[2], av.z, w1);                \
            FMA4(acc0[3], av.w, w0);  FMA4(acc1[3], av.w, w1);                \
        }                                                                     \
    } while (0)

#define ZEROACC()                                                             \
    do {                                                                      \
        _Pragma("unroll")                                                     \
        for (int _i = 0; _i < 4; _i++) {                                      \
            acc0[_i] = make_float4(0.f, 0.f, 0.f, 0.f);                       \
            acc1[_i] = make_float4(0.f, 0.f, 0.f, 0.f);                       \
        }                                                                     \
    } while (0)

// ---------------------------------------------------------------------------
// Fused: FFMA feature GEMMs (software-pipelined, double-buffered staging) +
// gates + two-level chunked scan (decoupled lookback) + output.
// CTA = 64 s-rows x 128 F, 256 threads, 2 CTAs/SM.
// Grid (BB, NCH): linear bid = ch*BB + b (chunk-major).
// ---------------------------------------------------------------------------
__global__ __launch_bounds__(256, 2)
void fused_sla(const float* __restrict__ q, const float* __restrict__ k,
               const float* __restrict__ v, const float* __restrict__ w,
               float* __restrict__ out)
{
    extern __shared__ float sm[];
    const int tid = threadIdx.x;
    const int tf  = tid & 15;
    const int s0  = (tid >> 4) * 4;
    const int b   = blockIdx.x;
    const int ch  = blockIdx.y;
    const int xbase = (tid >> 2) * 16 + (tid & 3);
    const size_t ibase = ((size_t)b * SS + ch * CS) * DD;

    float4 xr[4], acc0[4], acc1[4];

    LOADX(v + ibase);
    // W -> smem identity (coalesced)
#pragma unroll
    for (int t = 0; t < 8; t++)
        ((float4*)sm)[tid + t * 256] = ((const float4*)w)[tid + t * 256];
    STSE(0, SME0);
    __syncthreads();

    // ===== V GEMM =====
    ZEROACC();
    STSE(1, SME1); LOADX(k + ibase);
    FMAH(0, SME0);
    __syncthreads();
    STSE(0, SME0);               // K half0 into slab0
    FMAH(1, SME1);
#pragma unroll
    for (int i = 0; i < 4; i++) {
        const int row = s0 + i;
        *(float4*)&sm[SMV + row * 128 + tf * 4]      = acc0[i];
        *(float4*)&sm[SMV + row * 128 + 64 + tf * 4] = acc1[i];
    }
    __syncthreads();

    // ===== K GEMM =====
    ZEROACC();
    STSE(1, SME1); LOADX(q + ibase);
    FMAH(0, SME0);
    __syncthreads();
    STSE(0, SME0);               // Q half0 into slab0
    FMAH(1, SME1);
#pragma unroll
    for (int i = 0; i < 4; i++) {
        const int row = s0 + i;
        const float4 vf0 = *(const float4*)&sm[SMV + row * 128 + tf * 4];
        const float4 vf1 = *(const float4*)&sm[SMV + row * 128 + 64 + tf * 4];
        float4 a0, a1, c0, c1;
        GATE4(a0, acc0[i]);
        GATE4(a1, acc1[i]);
        c0.x = a0.x * vf0.x; c0.y = a0.y * vf0.y;
        c0.z = a0.z * vf0.z; c0.w = a0.w * vf0.w;
        c1.x = a1.x * vf1.x; c1.y = a1.y * vf1.y;
        c1.z = a1.z * vf1.z; c1.w = a1.w * vf1.w;
        *(float4*)&sm[SMA + row * 128 + tf * 4]      = a0;
        *(float4*)&sm[SMA + row * 128 + 64 + tf * 4] = a1;
        *(float4*)&sm[SMV + row * 128 + tf * 4]      = c0;
        *(float4*)&sm[SMV + row * 128 + 64 + tf * 4] = c1;
    }
    __syncthreads();

    // ===== local cumsums (two 32-row halves per column, in place) =====
    {
        const int col = tid & 127;
        const int r0  = (tid >> 7) * 32;
        float cA = 0.f, cC = 0.f;
#pragma unroll 8
        for (int s = 0; s < 32; s++) {
            cA += sm[SMA + (r0 + s) * 128 + col];
            sm[SMA + (r0 + s) * 128 + col] = cA;
            cC += sm[SMV + (r0 + s) * 128 + col];
            sm[SMV + (r0 + s) * 128 + col] = cC;
        }
    }
    __syncthreads();

    // ===== Q GEMM (agg publish overlapped with FMAH(0)) =====
    ZEROACC();
    if (tid < FF) {
        const float aggA = sm[SMA + 31 * 128 + tid] + sm[SMA + 63 * 128 + tid];
        const float aggC = sm[SMV + 31 * 128 + tid] + sm[SMV + 63 * 128 + tid];
        g_aggA[((size_t)ch * BB + b) * FF + tid] = aggA;
        g_aggC[((size_t)ch * BB + b) * FF + tid] = aggC;
        __threadfence();
    }
    STSE(1, SME1);
    FMAH(0, SME0);
    __syncthreads();
    if (tid == 0) atomicExch(&g_flag[ch * BB + b], 1);
    FMAH(1, SME1);
#pragma unroll
    for (int i = 0; i < 4; i++) {
        float4 t;
        GATE4(t, acc0[i]); acc0[i] = t;
        GATE4(t, acc1[i]); acc1[i] = t;
    }

    // ===== lookback wait (parallel) =====
    if (tid < ch)
        while (((volatile int*)g_flag)[tid * BB + b] == 0) __nanosleep(64);
    __syncthreads();

    // ===== prefix sums over predecessors -> prefbuf =====
    if (tid < FF) {
        float pA0 = 0.f, pA1 = 0.f, pC0 = 0.f, pC1 = 0.f;
        int p = 0;
        for (; p + 1 < ch; p += 2) {
            pA0 += g_aggA[((size_t)p * BB + b) * FF + tid];
            pA1 += g_aggA[((size_t)(p + 1) * BB + b) * FF + tid];
            pC0 += g_aggC[((size_t)p * BB + b) * FF + tid];
            pC1 += g_aggC[((size_t)(p + 1) * BB + b) * FF + tid];
        }
        if (p < ch) {
            pA0 += g_aggA[((size_t)p * BB + b) * FF + tid];
            pC0 += g_aggC[((size_t)p * BB + b) * FF + tid];
        }
        sm[SMPF  + tid] = pA0 + pA1;
        sm[SMPFC + tid] = pC0 + pC1;
    }
    __syncthreads();

    // ===== output: out = q_s * (C+eps)/(A+eps), fully parallel =====
    const size_t ob = ((size_t)b * SS + ch * CS) * FF;
    // per-column bases (prefix + lower-half total when in upper half)
    float4 bA0 = *(const float4*)&sm[SMPF + tf * 4];
    float4 bA1 = *(const float4*)&sm[SMPF + 64 + tf * 4];
    float4 bC0 = *(const float4*)&sm[SMPFC + tf * 4];
    float4 bC1 = *(const float4*)&sm[SMPFC + 64 + tf * 4];
    if (s0 >= 32) {
        const float4 lA0 = *(const float4*)&sm[SMA + 31 * 128 + tf * 4];
        const float4 lA1 = *(const float4*)&sm[SMA + 31 * 128 + 64 + tf * 4];
        const float4 lC0 = *(const float4*)&sm[SMV + 31 * 128 + tf * 4];
        const float4 lC1 = *(const float4*)&sm[SMV + 31 * 128 + 64 + tf * 4];
        bA0.x += lA0.x; bA0.y += lA0.y; bA0.z += lA0.z; bA0.w += lA0.w;
        bA1.x += lA1.x; bA1.y += lA1.y; bA1.z += lA1.z; bA1.w += lA1.w;
        bC0.x += lC0.x; bC0.y += lC0.y; bC0.z += lC0.z; bC0.w += lC0.w;
        bC1.x += lC1.x; bC1.y += lC1.y; bC1.z += lC1.z; bC1.w += lC1.w;
    }
#pragma unroll
    for (int i = 0; i < 4; i++) {
        const int row = s0 + i;
        const float4 a0 = *(const float4*)&sm[SMA + row * 128 + tf * 4];
        const float4 a1 = *(const float4*)&sm[SMA + row * 128 + 64 + tf * 4];
        const float4 c0 = *(const float4*)&sm[SMV + row * 128 + tf * 4];
        const float4 c1 = *(const float4*)&sm[SMV + row * 128 + 64 + tf * 4];
        float4 o0, o1;
        o0.x = acc0[i].x * __fdividef(bC0.x + c0.x + 1e-8f, bA0.x + a0.x + 1e-8f);
        o0.y = acc0[i].y * __fdividef(bC0.y + c0.y + 1e-8f, bA0.y + a0.y + 1e-8f);
        o0.z = acc0[i].z * __fdividef(bC0.z + c0.z + 1e-8f, bA0.z + a0.z + 1e-8f);
        o0.w = acc0[i].w * __fdividef(bC0.w + c0.w + 1e-8f, bA0.w + a0.w + 1e-8f);
        o1.x = acc1[i].x * __fdividef(bC1.x + c1.x + 1e-8f, bA1.x + a1.x + 1e-8f);
        o1.y = acc1[i].y * __fdividef(bC1.y + c1.y + 1e-8f, bA1.y + a1.y + 1e-8f);
        o1.z = acc1[i].z * __fdividef(bC1.z + c1.z + 1e-8f, bA1.z + a1.z + 1e-8f);
        o1.w = acc1[i].w * __fdividef(bC1.w + c1.w + 1e-8f, bA1.w + a1.w + 1e-8f);
        *(float4*)&out[ob + (size_t)row * FF + tf * 4]      = o0;
        *(float4*)&out[ob + (size_t)row * FF + 64 + tf * 4] = o1;
    }
}

extern "C" void kernel_launch(void* const* d_in, const int* in_sizes, int n_in,
                              void* d_out, int out_size)
{
    const float* q = (const float*)d_in[0];
    const float* k = (const float*)d_in[1];
    const float* v = (const float*)d_in[2];
    const float* w = (const float*)d_in[3];
    float* out = (float*)d_out;

    zero_flags<<<(NCH * BB + 255) / 256, 256>>>();

    cudaFuncSetAttribute(fused_sla, cudaFuncAttributeMaxDynamicSharedMemorySize,
                         SM_FLOATS * 4);
    dim3 grid(BB, NCH);   // linear bid = ch*BB + b (chunk-major)
    fused_sla<<<grid, 256, SM_FLOATS * 4>>>(q, k, v, w, out);
}

// round 8
// speedup vs baseline: 1.7373x; 1.0479x over previous
#include <cuda_runtime.h>
#include <cstdint>

#define BB 32
#define SS 8192
#define DD 64
#define FF 128
#define CS 64
#define NCH (SS / CS)   // 128 chunks

// Cross-CTA scan state (flags zeroed each launch)
__device__ float g_aggA[NCH * BB * FF];
__device__ float g_aggC[NCH * BB * FF];
__device__ int   g_flag[NCH * BB];

__global__ void zero_flags()
{
    const int i = blockIdx.x * 256 + threadIdx.x;
    if (i < NCH * BB) g_flag[i] = 0;
}

// SMEM float offsets (total 28928 floats = 113 KB -> 2 CTAs/SM)
#define SMW   0        // W: 64 k-rows x 128 cols              8192
#define SME0  8192     // E slab 0: 32 k x 64 s (pitch 68)     2176
#define SME1  10368    // E slab 1                             2176
#define SMA   12544    // A  (k_s -> cumsum): 64 x 128         8192
#define SMV   20736    // VC (v_f, c -> cumsum): 64 x 128      8192
#define SMPF  8192     // prefbuf A (reuses SME0 after Q GEMM)
#define SMPFC 8320     // prefbuf C
#define SM_FLOATS 28928

// ---- packed f32x2 helpers ----
__device__ __forceinline__ uint64_t pack2(float x) {
    uint64_t r;
    asm("mov.b64 %0, {%1, %1};" : "=l"(r) : "r"(__float_as_uint(x)));
    return r;
}
__device__ __forceinline__ float2 unpack2(uint64_t v) {
    uint32_t lo, hi;
    asm("mov.b64 {%0, %1}, %2;" : "=r"(lo), "=r"(hi) : "l"(v));
    return make_float2(__uint_as_float(lo), __uint_as_float(hi));
}
#define FMA2(d, a, b) \
    asm("fma.rn.f32x2 %0, %1, %2, %0;" : "+l"(d) : "l"(a), "l"(b))

#define GATE(x) (((x) > 0.5f) ? (x) : 0.f)

// Load whole 64x64 input tile into xr[8]: row = tid>>1, float4-col = (tid&1)+2j
#define LOADX(xptr)                                                           \
    do {                                                                      \
        const float4* _p4 = (const float4*)(xptr);                            \
        _Pragma("unroll")                                                     \
        for (int _j = 0; _j < 8; _j++)                                        \
            xr[_j] = _p4[xrow * 16 + xpar + 2 * _j];                          \
    } while (0)

// exp + store k-half h of xr into E slab (32 k x 64 s, pitch 68)
#define STSE(h, eb)                                                           \
    do {                                                                      \
        _Pragma("unroll")                                                     \
        for (int _jj = 0; _jj < 4; _jj++) {                                   \
            const float4 _x = xr[4 * (h) + _jj];                              \
            const int _kl = xpar * 4 + 8 * _jj;                               \
            sm[(eb) + (_kl + 0) * 68 + xrow] = __expf(_x.x);                  \
            sm[(eb) + (_kl + 1) * 68 + xrow] = __expf(_x.y);                  \
            sm[(eb) + (_kl + 2) * 68 + xrow] = __expf(_x.z);                  \
            sm[(eb) + (_kl + 3) * 68 + xrow] = __expf(_x.w);                  \
        }                                                                     \
    } while (0)

// FFMA2 over k-half h reading E slab at eb.
// acc[r][0..1]: cols [tf*4, +4); acc[r][2..3]: cols [64+tf*4, +4). r = row-s0.
#define FMAH(h, eb)                                                           \
    do {                                                                      \
        _Pragma("unroll 4")                                                   \
        for (int _kk = 0; _kk < 32; _kk++) {                                  \
            const float4 _av0 = *(const float4*)&sm[(eb) + _kk * 68 + s0];    \
            const float4 _av1 = *(const float4*)&sm[(eb) + _kk * 68 + s0 + 4];\
            const ulonglong2 _w0 = *(const ulonglong2*)&sm[SMW + ((h) * 32 + _kk) * 128 + tf * 4];      \
            const ulonglong2 _w1 = *(const ulonglong2*)&sm[SMW + ((h) * 32 + _kk) * 128 + 64 + tf * 4]; \
            uint64_t _ap[8];                                                  \
            _ap[0] = pack2(_av0.x); _ap[1] = pack2(_av0.y);                   \
            _ap[2] = pack2(_av0.z); _ap[3] = pack2(_av0.w);                   \
            _ap[4] = pack2(_av1.x); _ap[5] = pack2(_av1.y);                   \
            _ap[6] = pack2(_av1.z); _ap[7] = pack2(_av1.w);                   \
            _Pragma("unroll")                                                 \
            for (int _r = 0; _r < 8; _r++) {                                  \
                FMA2(acc[_r][0], _ap[_r], _w0.x);                             \
                FMA2(acc[_r][1], _ap[_r], _w0.y);                             \
                FMA2(acc[_r][2], _ap[_r], _w1.x);                             \
                FMA2(acc[_r][3], _ap[_r], _w1.y);                             \
            }                                                                 \
        }                                                                     \
    } while (0)

#define ZEROACC()                                                             \
    do {                                                                      \
        _Pragma("unroll") for (int _r = 0; _r < 8; _r++)                      \
        _Pragma("unroll") for (int _p = 0; _p < 4; _p++) acc[_r][_p] = 0ull;  \
    } while (0)

// ---------------------------------------------------------------------------
// Fused: FFMA2 feature GEMMs + gates + chunked scan (decoupled lookback) +
// output. CTA = 64 s-rows x 128 F, 128 threads (8x8 reg tile), 2 CTAs/SM.
// Grid (BB, NCH): linear bid = ch*BB + b (chunk-major).
// ---------------------------------------------------------------------------
__global__ __launch_bounds__(128, 2)
void fused_sla(const float* __restrict__ q, const float* __restrict__ k,
               const float* __restrict__ v, const float* __restrict__ w,
               float* __restrict__ out)
{
    extern __shared__ float sm[];
    const int tid  = threadIdx.x;
    const int tf   = tid & 15;          // col groups: [tf*4,+4) and [64+tf*4,+4)
    const int s0   = (tid >> 4) * 8;    // rows s0..s0+7
    const int xrow = tid >> 1;
    const int xpar = tid & 1;
    const int b    = blockIdx.x;
    const int ch   = blockIdx.y;
    const size_t ibase = ((size_t)b * SS + ch * CS) * DD;

    float4 xr[8];
    uint64_t acc[8][4];

    LOADX(v + ibase);
    // W -> smem identity (coalesced)
#pragma unroll
    for (int t = 0; t < 16; t++)
        ((float4*)sm)[tid + t * 128] = ((const float4*)w)[tid + t * 128];
    STSE(0, SME0);
    __syncthreads();

    // ===== V GEMM =====
    ZEROACC();
    STSE(1, SME1); LOADX(k + ibase);
    FMAH(0, SME0);
    __syncthreads();
    STSE(0, SME0);               // K half0 into slab0
    FMAH(1, SME1);
#pragma unroll
    for (int r = 0; r < 8; r++) {
        const int row = s0 + r;
        ulonglong2 t0; t0.x = acc[r][0]; t0.y = acc[r][1];
        ulonglong2 t1; t1.x = acc[r][2]; t1.y = acc[r][3];
        *(ulonglong2*)&sm[SMV + row * 128 + tf * 4]      = t0;
        *(ulonglong2*)&sm[SMV + row * 128 + 64 + tf * 4] = t1;
    }
    __syncthreads();

    // ===== K GEMM =====
    ZEROACC();
    STSE(1, SME1); LOADX(q + ibase);
    FMAH(0, SME0);
    __syncthreads();
    STSE(0, SME0);               // Q half0 into slab0
    FMAH(1, SME1);
#pragma unroll
    for (int r = 0; r < 8; r++) {
        const int row = s0 + r;
        const float2 k01 = unpack2(acc[r][0]);
        const float2 k23 = unpack2(acc[r][1]);
        const float2 k45 = unpack2(acc[r][2]);
        const float2 k67 = unpack2(acc[r][3]);
        const float4 vf0 = *(const float4*)&sm[SMV + row * 128 + tf * 4];
        const float4 vf1 = *(const float4*)&sm[SMV + row * 128 + 64 + tf * 4];
        float4 a0, a1, c0, c1;
        a0.x = GATE(k01.x); a0.y = GATE(k01.y);
        a0.z = GATE(k23.x); a0.w = GATE(k23.y);
        a1.x = GATE(k45.x); a1.y = GATE(k45.y);
        a1.z = GATE(k67.x); a1.w = GATE(k67.y);
        c0.x = a0.x * vf0.x; c0.y = a0.y * vf0.y;
        c0.z = a0.z * vf0.z; c0.w = a0.w * vf0.w;
        c1.x = a1.x * vf1.x; c1.y = a1.y * vf1.y;
        c1.z = a1.z * vf1.z; c1.w = a1.w * vf1.w;
        *(float4*)&sm[SMA + row * 128 + tf * 4]      = a0;
        *(float4*)&sm[SMA + row * 128 + 64 + tf * 4] = a1;
        *(float4*)&sm[SMV + row * 128 + tf * 4]      = c0;
        *(float4*)&sm[SMV + row * 128 + 64 + tf * 4] = c1;
    }
    __syncthreads();

    // ===== full in-chunk cumsum (1 thread/column); aggregate = final sums =====
    {
        float cA = 0.f, cC = 0.f;
#pragma unroll 8
        for (int s = 0; s < CS; s++) {
            cA += sm[SMA + s * 128 + tid];
            sm[SMA + s * 128 + tid] = cA;
            cC += sm[SMV + s * 128 + tid];
            sm[SMV + s * 128 + tid] = cC;
        }
        g_aggA[((size_t)ch * BB + b) * FF + tid] = cA;
        g_aggC[((size_t)ch * BB + b) * FF + tid] = cC;
        __threadfence();
    }
    __syncthreads();
    if (tid == 0) atomicExch(&g_flag[ch * BB + b], 1);

    // ===== Q GEMM =====
    ZEROACC();
    STSE(1, SME1);
    FMAH(0, SME0);
    __syncthreads();
    FMAH(1, SME1);

    // gate q_s into float registers
    float4 qsa[8], qsb[8];
#pragma unroll
    for (int r = 0; r < 8; r++) {
        const float2 q01 = unpack2(acc[r][0]);
        const float2 q23 = unpack2(acc[r][1]);
        const float2 q45 = unpack2(acc[r][2]);
        const float2 q67 = unpack2(acc[r][3]);
        qsa[r].x = GATE(q01.x); qsa[r].y = GATE(q01.y);
        qsa[r].z = GATE(q23.x); qsa[r].w = GATE(q23.y);
        qsb[r].x = GATE(q45.x); qsb[r].y = GATE(q45.y);
        qsb[r].z = GATE(q67.x); qsb[r].w = GATE(q67.y);
    }

    // ===== lookback wait (parallel) =====
    if (tid < ch)
        while (((volatile int*)g_flag)[tid * BB + b] == 0) __nanosleep(64);
    __syncthreads();

    // ===== prefix sums over predecessors -> prefbuf (reuses SME0) =====
    {
        float pA0 = 0.f, pA1 = 0.f, pC0 = 0.f, pC1 = 0.f;
        int p = 0;
        for (; p + 1 < ch; p += 2) {
            pA0 += g_aggA[((size_t)p * BB + b) * FF + tid];
            pA1 += g_aggA[((size_t)(p + 1) * BB + b) * FF + tid];
            pC0 += g_aggC[((size_t)p * BB + b) * FF + tid];
            pC1 += g_aggC[((size_t)(p + 1) * BB + b) * FF + tid];
        }
        if (p < ch) {
            pA0 += g_aggA[((size_t)p * BB + b) * FF + tid];
            pC0 += g_aggC[((size_t)p * BB + b) * FF + tid];
        }
        sm[SMPF  + tid] = pA0 + pA1;
        sm[SMPFC + tid] = pC0 + pC1;
    }
    __syncthreads();

    // ===== output: out = q_s * (prefC+cumC+eps)/(prefA+cumA+eps) =====
    const size_t ob = ((size_t)b * SS + ch * CS) * FF;
    const float4 bA0 = *(const float4*)&sm[SMPF + tf * 4];
    const float4 bA1 = *(const float4*)&sm[SMPF + 64 + tf * 4];
    const float4 bC0 = *(const float4*)&sm[SMPFC + tf * 4];
    const float4 bC1 = *(const float4*)&sm[SMPFC + 64 + tf * 4];
#pragma unroll
    for (int r = 0; r < 8; r++) {
        const int row = s0 + r;
        const float4 a0 = *(const float4*)&sm[SMA + row * 128 + tf * 4];
        const float4 a1 = *(const float4*)&sm[SMA + row * 128 + 64 + tf * 4];
        const float4 c0 = *(const float4*)&sm[SMV + row * 128 + tf * 4];
        const float4 c1 = *(const float4*)&sm[SMV + row * 128 + 64 + tf * 4];
        float4 o0, o1;
        o0.x = qsa[r].x * __fdividef(bC0.x + c0.x + 1e-8f, bA0.x + a0.x + 1e-8f);
        o0.y = qsa[r].y * __fdividef(bC0.y + c0.y + 1e-8f, bA0.y + a0.y + 1e-8f);
        o0.z = qsa[r].z * __fdividef(bC0.z + c0.z + 1e-8f, bA0.z + a0.z + 1e-8f);
        o0.w = qsa[r].w * __fdividef(bC0.w + c0.w + 1e-8f, bA0.w + a0.w + 1e-8f);
        o1.x = qsb[r].x * __fdividef(bC1.x + c1.x + 1e-8f, bA1.x + a1.x + 1e-8f);
        o1.y = qsb[r].y * __fdividef(bC1.y + c1.y + 1e-8f, bA1.y + a1.y + 1e-8f);
        o1.z = qsb[r].z * __fdividef(bC1.z + c1.z + 1e-8f, bA1.z + a1.z + 1e-8f);
        o1.w = qsb[r].w * __fdividef(bC1.w + c1.w + 1e-8f, bA1.w + a1.w + 1e-8f);
        *(float4*)&out[ob + (size_t)row * FF + tf * 4]      = o0;
        *(float4*)&out[ob + (size_t)row * FF + 64 + tf * 4] = o1;
    }
}

extern "C" void kernel_launch(void* const* d_in, const int* in_sizes, int n_in,
                              void* d_out, int out_size)
{
    const float* q = (const float*)d_in[0];
    const float* k = (const float*)d_in[1];
    const float* v = (const float*)d_in[2];
    const float* w = (const float*)d_in[3];
    float* out = (float*)d_out;

    zero_flags<<<(NCH * BB + 255) / 256, 256>>>();

    cudaFuncSetAttribute(fused_sla, cudaFuncAttributeMaxDynamicSharedMemorySize,
                         SM_FLOATS * 4);
    dim3 grid(BB, NCH);   // linear bid = ch*BB + b (chunk-major)
    fused_sla<<<grid, 128, SM_FLOATS * 4>>>(q, k, v, w, out);
}